// round 1
// baseline (speedup 1.0000x reference)
#include <cuda_runtime.h>

#define NB 96
#define ND 128
#define NPAIR (NB * NB)
#define QBLK 240
#define QTHR 256

// ---------------- device scratch (no allocations allowed) ----------------
__device__ float g_Dm[NPAIR];
__device__ float g_rowPos[NB];
__device__ float g_rowNeg[NB];
__device__ float g_thr;
__device__ float g_trip;
__device__ float g_pos_d[NPAIR];
__device__ int   g_pos_c[NPAIR];
__device__ float g_neg_d[NPAIR];
__device__ int   g_neg_c[NPAIR];
__device__ int   g_n_pos;
__device__ int   g_n_neg;
__device__ float g_qsum[QBLK];
__device__ unsigned int g_qcnt[QBLK];

// Labels may arrive as int64 (requested) or int32 (JAX x64-disabled demotion).
// Values are in [0, 8), so int64 high words are all zero. Reading 96 int32
// words is safe for either layout (384B <= min buffer size).
__device__ __forceinline__ int labels_are_i64(const int* w) {
    int all0 = 1;
#pragma unroll 1
    for (int t = 0; t < NB / 2; t++) all0 &= (w[2 * t + 1] == 0);
    return all0;
}
__device__ __forceinline__ int load_label(const void* labp, int i, int is64) {
    return is64 ? (int)((const long long*)labp)[i] : ((const int*)labp)[i];
}

// ---------------- K1: distance matrix + per-row masked sums ----------------
__global__ void k_dist(const float* __restrict__ E, const void* __restrict__ labp) {
    __shared__ float sRow[ND];
    __shared__ int sLab[NB];
    __shared__ float sRedP[4], sRedN[4];
    const int i = blockIdx.x;
    const int t = threadIdx.x;  // 128 threads

    const int is64 = labels_are_i64((const int*)labp);
    if (t < NB) sLab[t] = load_label(labp, t, is64);
    sRow[t] = E[i * ND + t];
    __syncthreads();

    float posv = 0.f, negv = 0.f;
    const int j = t;
    if (j < NB) {
        const float4* ej = (const float4*)(E + j * ND);
        float d2 = 0.f;
#pragma unroll
        for (int k = 0; k < ND / 4; k++) {
            float4 v = ej[k];
            float a = sRow[4 * k + 0] - v.x;
            float b = sRow[4 * k + 1] - v.y;
            float c = sRow[4 * k + 2] - v.z;
            float d = sRow[4 * k + 3] - v.w;
            d2 += a * a + b * b + c * c + d * d;
        }
        float dm = sqrtf(fmaxf(d2, 0.f) + 1e-16f);
        g_Dm[i * NB + j] = dm;
        if (j != i) {
            if (sLab[j] == sLab[i]) posv = dm; else negv = dm;
        }
    }
#pragma unroll
    for (int o = 16; o; o >>= 1) {
        posv += __shfl_down_sync(0xffffffffu, posv, o);
        negv += __shfl_down_sync(0xffffffffu, negv, o);
    }
    if ((t & 31) == 0) { sRedP[t >> 5] = posv; sRedN[t >> 5] = negv; }
    __syncthreads();
    if (t == 0) {
        g_rowPos[i] = sRedP[0] + sRedP[1] + sRedP[2] + sRedP[3];
        g_rowNeg[i] = sRedN[0] + sRedN[1] + sRedN[2] + sRedN[3];
    }
}

// ---------------- K2: thr, triplet loss, deterministic pair lists ----------------
__global__ void k_stats(const void* __restrict__ labp) {
    __shared__ float sDm[NPAIR];       // 36 KB
    __shared__ int sLab[NB];
    __shared__ float sThr;
    __shared__ int sPosOff[256], sNegOff[256];
    __shared__ float sRedF[8];
    __shared__ int sRedI[8];
    const int t = threadIdx.x;  // 256 threads

    const int is64 = labels_are_i64((const int*)labp);
    if (t < NB) sLab[t] = load_label(labp, t, is64);
    for (int idx = t; idx < NPAIR; idx += 256) sDm[idx] = g_Dm[idx];
    __syncthreads();

    if (t == 0) {
        int nc[8];
#pragma unroll
        for (int c = 0; c < 8; c++) nc[c] = 0;
        for (int i = 0; i < NB; i++) nc[sLab[i] & 7]++;
        int s2 = 0;
#pragma unroll
        for (int c = 0; c < 8; c++) s2 += nc[c] * nc[c];
        float cpos = (float)(s2 - NB);              // |{(i,j): i!=j, same label}|
        float cneg = (float)(NB * NB - s2);         // |{(i,j): diff label}|
        float ps = 0.f, ns = 0.f;
        for (int i = 0; i < NB; i++) { ps += g_rowPos[i]; ns += g_rowNeg[i]; }
        float mu = ns / cneg - ps / cpos;
        sThr = fmaxf(mu, 0.f);
        g_thr = sThr;
    }

    // pass 1: per-thread pair counts (deterministic list layout, no atomics)
    int myPos = 0, myNeg = 0;
    for (int idx = t; idx < NPAIR; idx += 256) {
        int i = idx / NB, j = idx - i * NB;
        if (i == j) continue;
        if (sLab[i] == sLab[j]) myPos++; else myNeg++;
    }
    sPosOff[t] = myPos; sNegOff[t] = myNeg;
    __syncthreads();
    if (t == 0) {
        int a = 0, b = 0;
        for (int u = 0; u < 256; u++) {
            int pa = sPosOff[u]; sPosOff[u] = a; a += pa;
            int nb2 = sNegOff[u]; sNegOff[u] = b; b += nb2;
        }
        g_n_pos = a; g_n_neg = b;
    }
    __syncthreads();

    const float thr = sThr;
    int po = sPosOff[t], no = sNegOff[t];
    float tsum = 0.f; int tcnt = 0;
    for (int idx = t; idx < NPAIR; idx += 256) {
        int i = idx / NB, j = idx - i * NB;
        if (i == j) continue;
        int li = sLab[i];
        float dij = sDm[idx];
        if (li == sLab[j]) {
            // positive pair (i,j): coupling class = label_j == label_i
            g_pos_d[po] = dij; g_pos_c[po] = li; po++;
            // triplet: anchor i, positive j, negatives k (label != li;
            // ne[i,k], ne[j,k] implied by label inequality)
            const float* drow = &sDm[i * NB];
            for (int k = 0; k < NB; k++) {
                if (sLab[k] != li) {
                    float tv = drow[k] - dij;
                    if (tv < thr) { tcnt++; tsum += fmaxf(tv, 0.f); }
                }
            }
        } else {
            // negative pair (k,l)=(i,j): coupling class = label of first index
            g_neg_d[no] = dij; g_neg_c[no] = li; no++;
        }
    }
#pragma unroll
    for (int o = 16; o; o >>= 1) {
        tsum += __shfl_down_sync(0xffffffffu, tsum, o);
        tcnt += __shfl_down_sync(0xffffffffu, tcnt, o);
    }
    if ((t & 31) == 0) { sRedF[t >> 5] = tsum; sRedI[t >> 5] = tcnt; }
    __syncthreads();
    if (t == 0) {
        float s = 0.f; int c = 0;
#pragma unroll
        for (int w = 0; w < 8; w++) { s += sRedF[w]; c += sRedI[w]; }
        g_trip = s / (float)c;
    }
}

// ---------------- K3: quadruplet = pos-pairs x neg-pairs cross product ----------------
__global__ void k_quad() {
    __shared__ float sS[QTHR / 32];
    __shared__ unsigned sC[QTHR / 32];
    const int npos = g_n_pos, nneg = g_n_neg;
    const float thrh = g_thr * 0.5f;
    float qs = 0.f; unsigned qc = 0;
    const int tg = blockIdx.x * QTHR + threadIdx.x;
    const int total = QBLK * QTHR;
    if (npos > 0 && nneg > 0) {
        int q = tg / npos;
        int p = tg - q * npos;
        const int stepq = total / npos;
        const int stepp = total - stepq * npos;
        while (q < nneg) {
            float b = g_neg_d[q];
            int cb = g_neg_c[q];
            float a = g_pos_d[p];
            int ca = g_pos_c[p];
            if (ca != cb) {                 // label_j != label_k coupling
                float qv = b - a;           // d_kl - d_ij
                if (qv < thrh) { qc++; qs += fmaxf(qv, 0.f); }
            }
            q += stepq; p += stepp;
            if (p >= npos) { p -= npos; q++; }
        }
    }
#pragma unroll
    for (int o = 16; o; o >>= 1) {
        qs += __shfl_down_sync(0xffffffffu, qs, o);
        qc += __shfl_down_sync(0xffffffffu, qc, o);
    }
    const int t = threadIdx.x;
    if ((t & 31) == 0) { sS[t >> 5] = qs; sC[t >> 5] = qc; }
    __syncthreads();
    if (t == 0) {
        float s = 0.f; unsigned c = 0;
#pragma unroll
        for (int w = 0; w < QTHR / 32; w++) { s += sS[w]; c += sC[w]; }
        g_qsum[blockIdx.x] = s;
        g_qcnt[blockIdx.x] = c;
    }
}

// ---------------- K4: combine ----------------
__global__ void k_final(float* __restrict__ out) {
    if (threadIdx.x == 0) {
        float s = 0.f, c = 0.f;
        for (int b = 0; b < QBLK; b++) { s += g_qsum[b]; c += (float)g_qcnt[b]; }
        out[0] = g_trip + s / c;
    }
}

extern "C" void kernel_launch(void* const* d_in, const int* in_sizes, int n_in,
                              void* d_out, int out_size) {
    const float* E = (const float*)d_in[0];
    const void* lab = d_in[1];
    (void)in_sizes; (void)n_in; (void)out_size;
    k_dist<<<NB, 128>>>(E, lab);
    k_stats<<<1, 256>>>(lab);
    k_quad<<<QBLK, QTHR>>>();
    k_final<<<1, 32>>>((float*)d_out);
}

// round 3
// speedup vs baseline: 5.3956x; 5.3956x over previous
#include <cuda_runtime.h>

#define NB 96
#define ND 128
#define NPAIR (NB * NB)
#define NCLS 8
#define CAP 4096
#define MBLK 148
#define MTHR 256

// ---------------- device scratch (no allocations allowed) ----------------
__device__ float g_Dm[NPAIR];
__device__ float g_rowPos[NB], g_rowNeg[NB];
__device__ float g_thr;
__device__ int   g_lab[NB];
__device__ float g_pos_d[NPAIR];
__device__ int   g_pos_m[NPAIR];     // anchor i | (class<<8)
__device__ float g_neg_d[NPAIR];
__device__ int   g_neg_c[NPAIR];
__device__ int   g_posOff[NCLS + 1], g_negOff[NCLS + 1];
__device__ int   g_ctrA = 0, g_ctrB = 0;
__device__ float g_pQ[MBLK], g_pT[MBLK];
__device__ unsigned g_pQC[MBLK], g_pTC[MBLK];

// =====================================================================
// Kernel A: distance matrix + per-row masked sums; the LAST-ARRIVING
// block builds thr and class-grouped pair lists (deterministic counting
// sort). Arrival-count pattern: no spinning, deadlock-free.
// =====================================================================
__global__ void kA(const float* __restrict__ E, const void* __restrict__ labp) {
    __shared__ float sRow[ND];
    __shared__ int   sLab[NB];
    __shared__ int   sIs64;
    __shared__ float sRP[8], sRN[8];
    __shared__ int   sLast;
    const int t = threadIdx.x;   // 256 threads
    const int i = blockIdx.x;    // 96 blocks

    if (t == 0) sIs64 = 1;
    __syncthreads();
    // labels are int64 (values < 8 => all high words 0) or int32 (JAX demotion)
    if (t < NB / 2) { if (((const int*)labp)[2 * t + 1] != 0) sIs64 = 0; }
    if (t < ND) sRow[t] = E[i * ND + t];
    __syncthreads();
    if (t < NB) sLab[t] = sIs64 ? (int)((const long long*)labp)[t]
                                : ((const int*)labp)[t];
    __syncthreads();

    float posv = 0.f, negv = 0.f;
    if (t < NB) {
        const float4* ej = (const float4*)(E + t * ND);
        float d2 = 0.f;
#pragma unroll
        for (int k = 0; k < ND / 4; k++) {
            float4 v = ej[k];
            float a = sRow[4 * k + 0] - v.x;
            float b = sRow[4 * k + 1] - v.y;
            float c = sRow[4 * k + 2] - v.z;
            float d = sRow[4 * k + 3] - v.w;
            d2 += a * a + b * b + c * c + d * d;
        }
        float dm = sqrtf(fmaxf(d2, 0.f) + 1e-16f);
        g_Dm[i * NB + t] = dm;
        if (t != i) { if (sLab[t] == sLab[i]) posv = dm; else negv = dm; }
    }
#pragma unroll
    for (int o = 16; o; o >>= 1) {
        posv += __shfl_down_sync(0xffffffffu, posv, o);
        negv += __shfl_down_sync(0xffffffffu, negv, o);
    }
    if ((t & 31) == 0) { sRP[t >> 5] = posv; sRN[t >> 5] = negv; }
    __syncthreads();
    if (t == 0) {
        float p = 0.f, n = 0.f;
#pragma unroll
        for (int w = 0; w < 8; w++) { p += sRP[w]; n += sRN[w]; }
        g_rowPos[i] = p; g_rowNeg[i] = n;
        __threadfence();
        sLast = (atomicAdd(&g_ctrA, 1) == NB - 1);
    }
    __syncthreads();
    if (!sLast) return;

    // ------------- build phase (last-arriving block only) -------------
    __shared__ unsigned short sCP[MTHR * NCLS], sCN[MTHR * NCLS];
    __shared__ int sTP[NCLS], sTN[NCLS];
    __shared__ int sPB[NCLS], sNBase[NCLS];
    for (int x = t; x < MTHR * NCLS; x += MTHR) { sCP[x] = 0; sCN[x] = 0; }
    __syncthreads();

    // pass 1: per-thread per-class pair counts
    for (int idx = t; idx < NPAIR; idx += MTHR) {
        int ii = idx / NB, jj = idx - ii * NB;
        if (ii == jj) continue;
        int li = sLab[ii];
        if (li == sLab[jj]) sCP[t * NCLS + li]++; else sCN[t * NCLS + li]++;
    }
    __syncthreads();

    // per-class exclusive scans over thread counts (one class per thread)
    if (t < NCLS) {
        int run = 0;
        for (int u = 0; u < MTHR; u++) {
            int v = sCP[u * NCLS + t];
            sCP[u * NCLS + t] = (unsigned short)run;
            run += v;
        }
        sTP[t] = run;
    } else if (t < 2 * NCLS) {
        int c = t - NCLS, run = 0;
        for (int u = 0; u < MTHR; u++) {
            int v = sCN[u * NCLS + c];
            sCN[u * NCLS + c] = (unsigned short)run;
            run += v;
        }
        sTN[c] = run;
    }
    __syncthreads();

    if (t == 0) {
        int a = 0, b = 0;
#pragma unroll
        for (int c = 0; c < NCLS; c++) {
            g_posOff[c] = a; sPB[c] = a; a += sTP[c];
            g_negOff[c] = b; sNBase[c] = b; b += sTN[c];
        }
        g_posOff[NCLS] = a; g_negOff[NCLS] = b;
        float ps = 0.f, ns = 0.f;
        for (int u = 0; u < NB; u++) { ps += g_rowPos[u]; ns += g_rowNeg[u]; }
        float mu = (b > 0 && a > 0) ? (ns / (float)b - ps / (float)a) : 0.f;
        g_thr = fmaxf(mu, 0.f);
    }
    __syncthreads();

    // pass 2: scatter into class-grouped lists (same traversal order as pass 1)
    for (int idx = t; idx < NPAIR; idx += MTHR) {
        int ii = idx / NB, jj = idx - ii * NB;
        if (ii == jj) continue;
        int li = sLab[ii];
        float dm = g_Dm[idx];
        if (li == sLab[jj]) {
            int s = sPB[li] + sCP[t * NCLS + li]; sCP[t * NCLS + li]++;
            g_pos_d[s] = dm;
            g_pos_m[s] = ii | (li << 8);
        } else {
            int s = sNBase[li] + sCN[t * NCLS + li]; sCN[t * NCLS + li]++;
            g_neg_d[s] = dm;
            g_neg_c[s] = li;
        }
    }
    if (t < NB) g_lab[t] = sLab[t];
    if (t == 0) g_ctrA = 0;   // reset arrival counter for next graph replay
}

// =====================================================================
// Kernel B: quadruplet (smem-resident pos list, class-segment skipping)
// + triplet (flattened over pos x NB); last-arriving block combines and
// writes the output (deterministic fixed-order reduction).
// =====================================================================
__global__ void __launch_bounds__(MTHR) kB(float* __restrict__ out) {
    __shared__ float sPD[CAP];
    __shared__ int   sPM[CAP];
    __shared__ int   sLab[NB];
    __shared__ int   sOff[NCLS + 1];
    __shared__ float sRF[8], sRF2[8];
    __shared__ unsigned sRC[8], sRC2[8];
    __shared__ int   sLast;
    const int t = threadIdx.x;

    if (t < NB) sLab[t] = g_lab[t];
    if (t <= NCLS) sOff[t] = g_posOff[t];
    __syncthreads();
    const int npos = sOff[NCLS];
    const int nneg = g_negOff[NCLS];
    const float thr = g_thr, thrh = 0.5f * thr;
    const bool useS = (npos <= CAP);
    if (useS) {
        for (int x = t; x < npos; x += MTHR) { sPD[x] = g_pos_d[x]; sPM[x] = g_pos_m[x]; }
    }
    __syncthreads();
    const float* pd = useS ? (const float*)sPD : g_pos_d;
    const int*   pm = useS ? (const int*)sPM   : g_pos_m;

    float qs = 0.f, ts = 0.f; unsigned qc = 0, tc = 0;
    const int gt = blockIdx.x * MTHR + t;
    const int GT = MBLK * MTHR;

    // ---- quadruplet: item = (neg pair q, pos class segment seg) ----
    const int qItems = nneg * NCLS;
    for (int e = gt; e < qItems; e += GT) {
        int q = e >> 3, seg = e & 7;
        int cb = g_neg_c[q];
        if (seg == cb) continue;      // label_j != label_k coupling via segments
        float b = g_neg_d[q];
        int x = sOff[seg];
        const int hi = sOff[seg + 1];
        // unroll-4 over the positive segment: raises LDS MLP over latency
        for (; x + 4 <= hi; x += 4) {
            float q0 = b - pd[x + 0];
            float q1 = b - pd[x + 1];
            float q2 = b - pd[x + 2];
            float q3 = b - pd[x + 3];
            if (q0 < thrh) { qc++; qs += fmaxf(q0, 0.f); }
            if (q1 < thrh) { qc++; qs += fmaxf(q1, 0.f); }
            if (q2 < thrh) { qc++; qs += fmaxf(q2, 0.f); }
            if (q3 < thrh) { qc++; qs += fmaxf(q3, 0.f); }
        }
        for (; x < hi; x++) {
            float qv = b - pd[x];     // d_kl - d_ij
            if (qv < thrh) { qc++; qs += fmaxf(qv, 0.f); }
        }
    }

    // ---- triplet: item = (pos pair pp, negative index k), division-free ----
    const int tItems = npos * NB;
    if (gt < tItems) {
        int pp = gt / NB, k = gt - pp * NB;
        const int stepP = GT / NB;            // GT = 37888 = 394*96 + 64
        const int stepK = GT - stepP * NB;
        int meta = pm[pp];
        int ai = meta & 255, c = meta >> 8;
        float dij = pd[pp];
        while (pp < npos) {
            if (sLab[k] != c) {               // implies k != i and k != j
                float tv = g_Dm[ai * NB + k] - dij;
                if (tv < thr) { tc++; ts += fmaxf(tv, 0.f); }
            }
            pp += stepP; k += stepK;
            if (k >= NB) { k -= NB; pp++; }
            if (pp < npos) {
                meta = pm[pp]; ai = meta & 255; c = meta >> 8; dij = pd[pp];
            }
        }
    }

    // ---- block reduction ----
#pragma unroll
    for (int o = 16; o; o >>= 1) {
        qs += __shfl_down_sync(0xffffffffu, qs, o);
        ts += __shfl_down_sync(0xffffffffu, ts, o);
        qc += __shfl_down_sync(0xffffffffu, qc, o);
        tc += __shfl_down_sync(0xffffffffu, tc, o);
    }
    if ((t & 31) == 0) { sRF[t >> 5] = qs; sRF2[t >> 5] = ts; sRC[t >> 5] = qc; sRC2[t >> 5] = tc; }
    __syncthreads();
    if (t == 0) {
        float a = 0.f, b = 0.f; unsigned c1 = 0, c2 = 0;
#pragma unroll
        for (int w = 0; w < 8; w++) { a += sRF[w]; b += sRF2[w]; c1 += sRC[w]; c2 += sRC2[w]; }
        g_pQ[blockIdx.x] = a; g_pT[blockIdx.x] = b;
        g_pQC[blockIdx.x] = c1; g_pTC[blockIdx.x] = c2;
        __threadfence();
        sLast = (atomicAdd(&g_ctrB, 1) == MBLK - 1);
    }
    __syncthreads();
    if (!sLast) return;

    // ---- final combine (last-arriving block, fixed-order) ----
    if (t < 32) {
        float a = 0.f, b = 0.f; unsigned c1 = 0, c2 = 0;
        for (int w = t; w < MBLK; w += 32) {
            a += g_pQ[w]; b += g_pT[w]; c1 += g_pQC[w]; c2 += g_pTC[w];
        }
#pragma unroll
        for (int o = 16; o; o >>= 1) {
            a  += __shfl_down_sync(0xffffffffu, a, o);
            b  += __shfl_down_sync(0xffffffffu, b, o);
            c1 += __shfl_down_sync(0xffffffffu, c1, o);
            c2 += __shfl_down_sync(0xffffffffu, c2, o);
        }
        if (t == 0) {
            float tl = (c2 > 0) ? b / (float)c2 : 0.f;
            float ql = (c1 > 0) ? a / (float)c1 : 0.f;
            out[0] = tl + ql;
            g_ctrB = 0;   // reset for next replay
        }
    }
}

extern "C" void kernel_launch(void* const* d_in, const int* in_sizes, int n_in,
                              void* d_out, int out_size) {
    const float* E = (const float*)d_in[0];
    const void* lab = d_in[1];
    (void)in_sizes; (void)n_in; (void)out_size;
    kA<<<NB, MTHR>>>(E, lab);
    kB<<<MBLK, MTHR>>>((float*)d_out);
}

// round 5
// speedup vs baseline: 6.1767x; 1.1447x over previous
#include <cuda_runtime.h>
#include <math_constants.h>

#define NB 96
#define ND 128
#define NPAIR (NB * NB)
#define NCLS 8
#define NUND 4560                 // NB*(NB-1)/2 undirected pairs
#define BTHR 1024
#define MAXBLK 160
#define POSCAP 4608               // worst-case undirected pos + segment padding
#define NEGCAP 9216

// ---------------- device scratch (no allocations allowed) ----------------
__device__ float g_Dm[NPAIR];
__device__ __align__(16) float g_pos_d[POSCAP];
__device__ int   g_pos_m[POSCAP];          // i | (j<<8) | (class<<16)
__device__ float g_neg_d[NEGCAP];
__device__ int   g_neg_c[NEGCAP];
__device__ int   g_base[NCLS + 1];         // aligned pos class bases; [8] = padded total
__device__ int   g_nneg;
__device__ float g_thr;
__device__ int   g_ctrA = 0, g_ctrB = 0;
__device__ volatile int g_flagA = 0;
__device__ float g_pQ[MAXBLK], g_pT[MAXBLK];
__device__ unsigned g_pQC[MAXBLK], g_pTC[MAXBLK];

__device__ __forceinline__ void blk_reduce4(float& a, float& b, unsigned& c1, unsigned& c2,
                                            float* sF1, float* sF2, unsigned* sC1, unsigned* sC2,
                                            int t) {
#pragma unroll
    for (int o = 16; o; o >>= 1) {
        a  += __shfl_down_sync(0xffffffffu, a, o);
        b  += __shfl_down_sync(0xffffffffu, b, o);
        c1 += __shfl_down_sync(0xffffffffu, c1, o);
        c2 += __shfl_down_sync(0xffffffffu, c2, o);
    }
    if ((t & 31) == 0) { sF1[t >> 5] = a; sF2[t >> 5] = b; sC1[t >> 5] = c1; sC2[t >> 5] = c2; }
    __syncthreads();
    if (t < 32) {
        a = sF1[t]; b = sF2[t]; c1 = sC1[t]; c2 = sC2[t];
#pragma unroll
        for (int o = 16; o; o >>= 1) {
            a  += __shfl_down_sync(0xffffffffu, a, o);
            b  += __shfl_down_sync(0xffffffffu, b, o);
            c1 += __shfl_down_sync(0xffffffffu, c1, o);
            c2 += __shfl_down_sync(0xffffffffu, c2, o);
        }
    }
}

__global__ void __launch_bounds__(BTHR, 1)
kFused(const float* __restrict__ E, const void* __restrict__ labp,
       float* __restrict__ out) {
    __shared__ int   sLab[NB];
    __shared__ int   sIs64;
    __shared__ int   sBuild;
    __shared__ int   sOff[NCLS + 1];
    __shared__ __align__(16) float sPD[POSCAP];   // 16B-aligned: segment bases are
    __shared__ int   sPM[POSCAP];                 // 4-elem aligned => LDS.128 legal
    __shared__ unsigned short sCP[NCLS * 256], sCN[NCLS * 256];
    __shared__ int   sTotP[NCLS], sTotN[NCLS];
    __shared__ int   sBaseP[NCLS], sBaseN[NCLS];
    __shared__ float sF1[32], sF2[32];
    __shared__ unsigned sC1[32], sC2[32];
    __shared__ int   sNposReal, sNneg, sBase8;

    const int t = threadIdx.x;
    const int wid = t >> 5, lid = t & 31;
    const int nblk = gridDim.x;

    // ---- labels (int64 with zero high words, or int32 after JAX demotion) ----
    if (t == 0) sIs64 = 1;
    __syncthreads();
    if (t < NB / 2) { if (((const int*)labp)[2 * t + 1] != 0) sIs64 = 0; }
    __syncthreads();
    if (t < NB) sLab[t] = sIs64 ? (int)((const long long*)labp)[t]
                                : ((const int*)labp)[t];
    __syncthreads();

    // ================= Phase 1: distance matrix (warp per pair) =================
    for (int p = blockIdx.x * 32 + wid; p < NUND; p += nblk * 32) {
        // decode undirected pair p -> (i, j), i < j ; T(i) = i*(191 - i)/2
        float s = sqrtf((float)(36481 - 8 * p));
        int i = (int)((191.0f - s) * 0.5f);
        while ((i + 1) * (191 - (i + 1)) / 2 <= p) ++i;
        while (i * (191 - i) / 2 > p) --i;
        int j = i + 1 + (p - i * (191 - i) / 2);
        const float4 a = ((const float4*)(E + i * ND))[lid];
        const float4 b = ((const float4*)(E + j * ND))[lid];
        float dx = a.x - b.x, dy = a.y - b.y, dz = a.z - b.z, dw = a.w - b.w;
        float d2 = dx * dx + dy * dy + dz * dz + dw * dw;
#pragma unroll
        for (int o = 16; o; o >>= 1) d2 += __shfl_down_sync(0xffffffffu, d2, o);
        if (lid == 0) {
            float dm = sqrtf(fmaxf(d2, 0.f) + 1e-16f);
            g_Dm[i * NB + j] = dm;
            g_Dm[j * NB + i] = dm;
        }
    }
    __syncthreads();

    // ================= barrier A: last-arriving block builds =================
    if (t == 0) {
        __threadfence();
        sBuild = (atomicAdd(&g_ctrA, 1) == nblk - 1);
    }
    __syncthreads();

    if (sBuild) {
        // ---- pass 1: per-thread per-class counts (threads 0..255) ----
        int cP[NCLS], cN[NCLS];
#pragma unroll
        for (int c = 0; c < NCLS; c++) { cP[c] = 0; cN[c] = 0; }
        if (t < 256) {
            for (int idx = t; idx < NPAIR; idx += 256) {
                int ii = idx / NB, jj = idx - ii * NB;
                if (ii == jj) continue;
                int li = sLab[ii];
                if (li == sLab[jj]) { if (ii < jj) cP[li]++; }
                else cN[li]++;
            }
#pragma unroll
            for (int c = 0; c < NCLS; c++) {
                sCP[c * 256 + t] = (unsigned short)cP[c];
                sCN[c * 256 + t] = (unsigned short)cN[c];
            }
        }
        __syncthreads();

        // ---- per-class exclusive scans: warps 0..7 pos, warps 8..15 neg ----
        if (wid < 16) {
            const int c = wid & 7;
            unsigned short* arr = (wid < 8) ? (sCP + c * 256) : (sCN + c * 256);
            int v[8], s = 0;
#pragma unroll
            for (int k = 0; k < 8; k++) { v[k] = arr[8 * lid + k]; s += v[k]; }
            int inc = s;
#pragma unroll
            for (int o = 1; o < 32; o <<= 1) {
                int x = __shfl_up_sync(0xffffffffu, inc, o);
                if (lid >= o) inc += x;
            }
            int run = inc - s;
#pragma unroll
            for (int k = 0; k < 8; k++) { arr[8 * lid + k] = (unsigned short)run; run += v[k]; }
            if (lid == 31) { if (wid < 8) sTotP[c] = inc; else sTotN[c] = inc; }
        }
        __syncthreads();

        if (t == 0) {
            int b = 0, nb2 = 0, nreal = 0;
#pragma unroll
            for (int c = 0; c < NCLS; c++) {
                sBaseP[c] = b; g_base[c] = b;
                nreal += sTotP[c];
                b = (b + sTotP[c] + 3) & ~3;           // align next base to 4 elems
                sBaseN[c] = nb2; nb2 += sTotN[c];
            }
            g_base[NCLS] = b; sBase8 = b;
            g_nneg = nb2; sNneg = nb2; sNposReal = nreal;
        }
        __syncthreads();

        // ---- init pos arrays with -INF sentinels (pads self-neutralize) ----
        for (int x = t; x < sBase8; x += BTHR) { g_pos_d[x] = -CUDART_INF_F; g_pos_m[x] = 0; }
        __syncthreads();

        // ---- pass 2: scatter (same traversal order as pass 1) ----
        if (t < 256) {
            for (int idx = t; idx < NPAIR; idx += 256) {
                int ii = idx / NB, jj = idx - ii * NB;
                if (ii == jj) continue;
                int li = sLab[ii];
                if (li == sLab[jj]) {
                    if (ii < jj) {
                        int s2 = sBaseP[li] + sCP[li * 256 + t]; sCP[li * 256 + t]++;
                        g_pos_d[s2] = g_Dm[idx];
                        g_pos_m[s2] = ii | (jj << 8) | (li << 16);
                    }
                } else {
                    int s2 = sBaseN[li] + sCN[li * 256 + t]; sCN[li * 256 + t]++;
                    g_neg_d[s2] = g_Dm[idx];
                    g_neg_c[s2] = li;
                }
            }
        }
        __syncthreads();

        // ---- mu / thr ----
        float ps = 0.f, ns = 0.f; unsigned d1 = 0, d2 = 0;
        for (int x = t; x < sBase8; x += BTHR) {
            float v = g_pos_d[x];
            if (v > -1e30f) ps += v;
        }
        for (int x = t; x < sNneg; x += BTHR) ns += g_neg_d[x];
        blk_reduce4(ps, ns, d1, d2, sF1, sF2, sC1, sC2, t);
        if (t == 0) {
            float mu = (sNneg > 0 && sNposReal > 0)
                       ? (ns / (float)sNneg - ps / (float)sNposReal) : 0.f;
            g_thr = fmaxf(mu, 0.f);
            __threadfence();
            g_flagA = 1;                       // release
        }
        __syncthreads();
    } else {
        if (t == 0) {
            while (g_flagA == 0) __nanosleep(64);
            __threadfence();                   // acquire
        }
        __syncthreads();
    }

    // ================= Phase 2: quad + triplet =================
    if (t <= NCLS) sOff[t] = g_base[t];
    __syncthreads();
    const int base8 = sOff[NCLS];
    const int nneg = g_nneg;
    const float thr = g_thr, thrh = 0.5f * thr;
    for (int x = t; x < base8; x += BTHR) { sPD[x] = g_pos_d[x]; sPM[x] = g_pos_m[x]; }
    __syncthreads();

    float qs0 = 0.f, qs1 = 0.f, qs2 = 0.f, qs3 = 0.f, ts = 0.f;
    unsigned qc0 = 0, qc1 = 0, qc2 = 0, qc3 = 0, tc = 0;
    const int gt = blockIdx.x * BTHR + t;
    const int GT = nblk * BTHR;

    // ---- quadruplet: item = (neg pair q, pos class segment seg) ----
    const int qItems = nneg * NCLS;
    for (int e = gt; e < qItems; e += GT) {
        int q = e >> 3, seg = e & 7;
        if (seg == g_neg_c[q]) continue;       // label_j != label_k via segments
        float b = g_neg_d[q];
        const int lo = sOff[seg], hi = sOff[seg + 1];   // both 4-elem aligned
        for (int x = lo; x < hi; x += 4) {
            const float4 v = *reinterpret_cast<const float4*>(&sPD[x]);
            float d0 = b - v.x, d1v = b - v.y, d2v = b - v.z, d3 = b - v.w;
            if (d0  < thrh) { qc0++; qs0 += fmaxf(d0, 0.f); }
            if (d1v < thrh) { qc1++; qs1 += fmaxf(d1v, 0.f); }
            if (d2v < thrh) { qc2++; qs2 += fmaxf(d2v, 0.f); }
            if (d3  < thrh) { qc3++; qs3 += fmaxf(d3, 0.f); }
        }
    }
    float qs = (qs0 + qs1) + (qs2 + qs3);
    unsigned qc = (qc0 + qc1) + (qc2 + qc3);

    // ---- triplet: item = (padded pos slot pp, negative k); both anchors ----
    const int tItems = base8 * NB;
    for (int e = gt; e < tItems; e += GT) {
        int pp = e / NB, k = e - pp * NB;
        int meta = sPM[pp];
        int ai = meta & 255, aj = (meta >> 8) & 255, c = meta >> 16;
        float dij = sPD[pp];                   // -INF pads => tv = +INF => skipped
        if (sLab[k] != c) {
            float tv1 = g_Dm[ai * NB + k] - dij;
            float tv2 = g_Dm[aj * NB + k] - dij;
            if (tv1 < thr) { tc++; ts += fmaxf(tv1, 0.f); }
            if (tv2 < thr) { tc++; ts += fmaxf(tv2, 0.f); }
        }
    }

    // ================= Phase 3: reduce + combine =================
    blk_reduce4(qs, ts, qc, tc, sF1, sF2, sC1, sC2, t);
    __syncthreads();
    if (t == 0) {
        g_pQ[blockIdx.x] = qs; g_pT[blockIdx.x] = ts;
        g_pQC[blockIdx.x] = qc; g_pTC[blockIdx.x] = tc;
        __threadfence();
        sBuild = (atomicAdd(&g_ctrB, 1) == nblk - 1);
    }
    __syncthreads();
    if (!sBuild) return;

    if (t < 32) {
        float a = 0.f, b = 0.f; unsigned c1 = 0, c2 = 0;
        for (int w = t; w < nblk; w += 32) {
            a += g_pQ[w]; b += g_pT[w]; c1 += g_pQC[w]; c2 += g_pTC[w];
        }
#pragma unroll
        for (int o = 16; o; o >>= 1) {
            a  += __shfl_down_sync(0xffffffffu, a, o);
            b  += __shfl_down_sync(0xffffffffu, b, o);
            c1 += __shfl_down_sync(0xffffffffu, c1, o);
            c2 += __shfl_down_sync(0xffffffffu, c2, o);
        }
        if (t == 0) {
            float tl = (c2 > 0) ? b / (float)c2 : 0.f;
            float ql = (c1 > 0) ? a / (float)c1 : 0.f;
            out[0] = tl + ql;
            g_ctrA = 0; g_ctrB = 0; g_flagA = 0;   // reset for next replay
        }
    }
}

extern "C" void kernel_launch(void* const* d_in, const int* in_sizes, int n_in,
                              void* d_out, int out_size) {
    const float* E = (const float*)d_in[0];
    const void* lab = d_in[1];
    (void)in_sizes; (void)n_in; (void)out_size;
    int sms = 148;
    cudaDeviceGetAttribute(&sms, cudaDevAttrMultiProcessorCount, 0);
    int grid = sms < MAXBLK ? sms : MAXBLK;    // single wave => spin barrier safe
    kFused<<<grid, BTHR>>>(E, lab, (float*)d_out);
}

// round 7
// speedup vs baseline: 10.0088x; 1.6204x over previous
#include <cuda_runtime.h>
#include <math_constants.h>

#define NB 96
#define ND 128
#define NPAIR (NB * NB)
#define NCLS 8
#define NUND 4560                 // NB*(NB-1)/2 undirected pairs
#define BTHR 1024
#define MAXBLK 160
#define POSC 1536                 // smem pos-list capacity (expected npos ~570)
#define GPOSC 4608                // global fallback capacity (worst case)

// dynamic smem layout (bytes): [0) Dm 36864 | sPD 6144 | sPM 6144  = 49152
#define DYN_SMEM 49152

// ---------------- device scratch (no allocations allowed) ----------------
__device__ float g_Dm[NPAIR];
__device__ __align__(16) float g_fb_d[GPOSC];   // fallback pos list (identical-value writes)
__device__ int   g_fb_m[GPOSC];
__device__ int   g_ctrA = 0, g_ctrB = 0;
__device__ volatile int g_flagA = 0;
__device__ float g_pQ[MAXBLK], g_pT[MAXBLK];
__device__ unsigned g_pQC[MAXBLK], g_pTC[MAXBLK];

__device__ __forceinline__ void blk_reduce4(float& a, float& b, unsigned& c1, unsigned& c2,
                                            float* sF1, float* sF2, unsigned* sC1, unsigned* sC2,
                                            int t) {
#pragma unroll
    for (int o = 16; o; o >>= 1) {
        a  += __shfl_down_sync(0xffffffffu, a, o);
        b  += __shfl_down_sync(0xffffffffu, b, o);
        c1 += __shfl_down_sync(0xffffffffu, c1, o);
        c2 += __shfl_down_sync(0xffffffffu, c2, o);
    }
    if ((t & 31) == 0) { sF1[t >> 5] = a; sF2[t >> 5] = b; sC1[t >> 5] = c1; sC2[t >> 5] = c2; }
    __syncthreads();
    if (t < 32) {
        a = sF1[t]; b = sF2[t]; c1 = sC1[t]; c2 = sC2[t];
#pragma unroll
        for (int o = 16; o; o >>= 1) {
            a  += __shfl_down_sync(0xffffffffu, a, o);
            b  += __shfl_down_sync(0xffffffffu, b, o);
            c1 += __shfl_down_sync(0xffffffffu, c1, o);
            c2 += __shfl_down_sync(0xffffffffu, c2, o);
        }
    }
}

__global__ void __launch_bounds__(BTHR, 1)
kFused(const float* __restrict__ E, const void* __restrict__ labp,
       float* __restrict__ out) {
    extern __shared__ __align__(16) unsigned char dynRaw[];
    float* sDm = reinterpret_cast<float*>(dynRaw);                       // [NPAIR]
    float* sPD = reinterpret_cast<float*>(dynRaw + NPAIR * 4);           // [POSC]
    int*   sPM = reinterpret_cast<int*>(dynRaw + NPAIR * 4 + POSC * 4);  // [POSC]

    __shared__ int   sLab[NB];
    __shared__ int   sIs64;
    __shared__ unsigned short sCP[NCLS * 256];
    __shared__ int   sTot[NCLS], sBase[NCLS];
    __shared__ int   sOff[NCLS + 1];
    __shared__ float sF1[32], sF2[32];
    __shared__ unsigned sC1[32], sC2[32];
    __shared__ float sThr;
    __shared__ int   sUseS, sLastFlag;

    const int t = threadIdx.x;
    const int wid = t >> 5, lid = t & 31;
    const int nblk = gridDim.x;

    // ---- labels (int64 with zero high words, or int32 after JAX demotion) ----
    if (t == 0) sIs64 = 1;
    __syncthreads();
    if (t < NB / 2) { if (((const int*)labp)[2 * t + 1] != 0) sIs64 = 0; }
    __syncthreads();
    if (t < NB) sLab[t] = sIs64 ? (int)((const long long*)labp)[t]
                                : ((const int*)labp)[t];
    __syncthreads();

    // ================= Phase 1: cooperative distance matrix =================
    for (int p = blockIdx.x * 32 + wid; p < NUND; p += nblk * 32) {
        // decode undirected pair p -> (i, j), i < j ; offset(i) = i*(191-i)/2
        float s = sqrtf((float)(36481 - 8 * p));
        int i = (int)((191.0f - s) * 0.5f);
        while ((i + 1) * (191 - (i + 1)) / 2 <= p) ++i;
        while (i * (191 - i) / 2 > p) --i;
        int j = i + 1 + (p - i * (191 - i) / 2);
        const float4 a = ((const float4*)(E + i * ND))[lid];
        const float4 b = ((const float4*)(E + j * ND))[lid];
        float dx = a.x - b.x, dy = a.y - b.y, dz = a.z - b.z, dw = a.w - b.w;
        float d2 = dx * dx + dy * dy + dz * dz + dw * dw;
#pragma unroll
        for (int o = 16; o; o >>= 1) d2 += __shfl_down_sync(0xffffffffu, d2, o);
        if (lid == 0) {
            float dm = sqrtf(fmaxf(d2, 0.f) + 1e-16f);
            g_Dm[i * NB + j] = dm;
            g_Dm[j * NB + i] = dm;
        }
    }
    // diagonal: written for completeness; every consumer masks ii==jj first
    if (t < NB && blockIdx.x == 0) g_Dm[t * NB + t] = 1e-8f;
    __syncthreads();

    // ================= barrier A (only global sync; grid is residency-clamped) ===
    if (t == 0) {
        __threadfence();
        if (atomicAdd(&g_ctrA, 1) == nblk - 1) {
            g_flagA = 1;                       // last arriver releases everyone
        } else {
            while (g_flagA == 0) __nanosleep(64);
        }
        __threadfence();
    }
    __syncthreads();

    // ================= Phase 2: per-block redundant build (all smem) =================
    {
        float4* s4 = reinterpret_cast<float4*>(sDm);
        const float4* g4 = reinterpret_cast<const float4*>(g_Dm);
        for (int x = t; x < NPAIR / 4; x += BTHR) s4[x] = g4[x];
    }
    __syncthreads();

    // thr: masked means over directed pairs (deterministic, identical per block)
    {
        float ps = 0.f, ns = 0.f; unsigned pc = 0, nc = 0;
        for (int idx = t; idx < NPAIR; idx += BTHR) {
            int ii = idx / NB, jj = idx - ii * NB;
            if (ii == jj) continue;
            float v = sDm[idx];
            if (sLab[ii] == sLab[jj]) { ps += v; pc++; } else { ns += v; nc++; }
        }
        blk_reduce4(ps, ns, pc, nc, sF1, sF2, sC1, sC2, t);
        if (t == 0) {
            float mu = (pc > 0 && nc > 0) ? (ns / (float)nc - ps / (float)pc) : 0.f;
            sThr = fmaxf(mu, 0.f);
        }
        __syncthreads();
    }

    // pos-list build: two-pass counting sort by class (threads 0..255; deterministic)
    {
        int cnt[NCLS];
#pragma unroll
        for (int c = 0; c < NCLS; c++) cnt[c] = 0;
        if (t < 256) {
            for (int idx = t; idx < NPAIR; idx += 256) {
                int ii = idx / NB, jj = idx - ii * NB;
                if (ii < jj && sLab[ii] == sLab[jj]) cnt[sLab[ii]]++;
            }
#pragma unroll
            for (int c = 0; c < NCLS; c++) sCP[c * 256 + t] = (unsigned short)cnt[c];
        }
        __syncthreads();
        if (wid < NCLS) {   // warp per class: exclusive scan of 256 counters
            unsigned short* arr = sCP + wid * 256;
            int v[8], s = 0;
#pragma unroll
            for (int k = 0; k < 8; k++) { v[k] = arr[8 * lid + k]; s += v[k]; }
            int inc = s;
#pragma unroll
            for (int o = 1; o < 32; o <<= 1) {
                int x = __shfl_up_sync(0xffffffffu, inc, o);
                if (lid >= o) inc += x;
            }
            int run = inc - s;
#pragma unroll
            for (int k = 0; k < 8; k++) { arr[8 * lid + k] = (unsigned short)run; run += v[k]; }
            if (lid == 31) sTot[wid] = inc;
        }
        __syncthreads();
        if (t == 0) {
            int b = 0;
#pragma unroll
            for (int c = 0; c < NCLS; c++) {
                sBase[c] = b; sOff[c] = b;
                b = (b + sTot[c] + 3) & ~3;            // 4-elem aligned segments
            }
            sOff[NCLS] = b;
            sUseS = (b <= POSC);
        }
        __syncthreads();
        const int base8 = sOff[NCLS];
        float* pdW = sUseS ? sPD : g_fb_d;
        int*   pmW = sUseS ? sPM : g_fb_m;
        for (int x = t; x < base8; x += BTHR) { pdW[x] = -CUDART_INF_F; pmW[x] = 0; }
        __syncthreads();
        if (t < 256) {        // scatter, identical traversal order as pass 1
            int off[NCLS];
#pragma unroll
            for (int c = 0; c < NCLS; c++) off[c] = sBase[c] + (int)sCP[c * 256 + t];
            for (int idx = t; idx < NPAIR; idx += 256) {
                int ii = idx / NB, jj = idx - ii * NB;
                if (ii < jj && sLab[ii] == sLab[jj]) {
                    int c = sLab[ii];
                    int s2 = off[c]++;
                    pdW[s2] = sDm[idx];
                    pmW[s2] = ii | (jj << 8) | (c << 16);
                }
            }
        }
        __syncthreads();
    }

    const int base8 = sOff[NCLS];
    const float thr = sThr, thrh = 0.5f * thr;
    const float* pd = sUseS ? (const float*)sPD : (const float*)g_fb_d;
    const int*   pm = sUseS ? (const int*)sPM   : (const int*)g_fb_m;

    // ================= Phase 3: quad + triplet =================
    float qs0 = 0.f, qs1 = 0.f, qs2 = 0.f, qs3 = 0.f, ts = 0.f;
    unsigned qc0 = 0, qc1 = 0, qc2 = 0, qc3 = 0, tc = 0;
    const int gt = blockIdx.x * BTHR + t;
    const int GT = nblk * BTHR;

    // quad: item = (directed pair idx, pos class segment seg); neg pairs only
    for (int e = gt; e < NPAIR * NCLS; e += GT) {
        int idx = e >> 3, seg = e & 7;
        int ii = idx / NB, jj = idx - ii * NB;
        int cb = sLab[ii];
        if (sLab[jj] == cb) continue;           // not a negative pair (covers ii==jj)
        if (seg == cb) continue;                // label_j != label_k coupling
        float b = sDm[idx];
        const int lo = sOff[seg], hi = sOff[seg + 1];
        for (int x = lo; x < hi; x += 4) {
            float v0 = pd[x + 0], v1 = pd[x + 1], v2 = pd[x + 2], v3 = pd[x + 3];
            float d0 = b - v0, d1 = b - v1, d2 = b - v2, d3 = b - v3;
            if (d0 < thrh) { qc0++; qs0 += fmaxf(d0, 0.f); }
            if (d1 < thrh) { qc1++; qs1 += fmaxf(d1, 0.f); }
            if (d2 < thrh) { qc2++; qs2 += fmaxf(d2, 0.f); }
            if (d3 < thrh) { qc3++; qs3 += fmaxf(d3, 0.f); }
        }
    }
    float qs = (qs0 + qs1) + (qs2 + qs3);
    unsigned qc = (qc0 + qc1) + (qc2 + qc3);

    // triplet: item = (padded pos slot pp, negative k); both anchor orientations
    for (int e = gt; e < base8 * NB; e += GT) {
        int pp = e / NB, k = e - pp * NB;
        int meta = pm[pp];
        int ai = meta & 255, aj = (meta >> 8) & 255, c = meta >> 16;
        float dij = pd[pp];                     // -INF pads => +INF diffs => skipped
        if (sLab[k] != c) {
            float tv1 = sDm[ai * NB + k] - dij;
            float tv2 = sDm[aj * NB + k] - dij;
            if (tv1 < thr) { tc++; ts += fmaxf(tv1, 0.f); }
            if (tv2 < thr) { tc++; ts += fmaxf(tv2, 0.f); }
        }
    }

    // ================= Phase 4: reduce + combine =================
    blk_reduce4(qs, ts, qc, tc, sF1, sF2, sC1, sC2, t);
    __syncthreads();
    if (t == 0) {
        g_pQ[blockIdx.x] = qs; g_pT[blockIdx.x] = ts;
        g_pQC[blockIdx.x] = qc; g_pTC[blockIdx.x] = tc;
        __threadfence();
        sLastFlag = (atomicAdd(&g_ctrB, 1) == nblk - 1);
    }
    __syncthreads();
    if (!sLastFlag) return;

    if (t < 32) {
        float a = 0.f, b = 0.f; unsigned c1 = 0, c2 = 0;
        for (int w = t; w < nblk; w += 32) {
            a += g_pQ[w]; b += g_pT[w]; c1 += g_pQC[w]; c2 += g_pTC[w];
        }
#pragma unroll
        for (int o = 16; o; o >>= 1) {
            a  += __shfl_down_sync(0xffffffffu, a, o);
            b  += __shfl_down_sync(0xffffffffu, b, o);
            c1 += __shfl_down_sync(0xffffffffu, c1, o);
            c2 += __shfl_down_sync(0xffffffffu, c2, o);
        }
        if (t == 0) {
            float tl = (c2 > 0) ? b / (float)c2 : 0.f;
            float ql = (c1 > 0) ? a / (float)c1 : 0.f;
            out[0] = tl + ql;
            g_ctrA = 0; g_ctrB = 0; g_flagA = 0;   // reset for next replay
        }
    }
}

extern "C" void kernel_launch(void* const* d_in, const int* in_sizes, int n_in,
                              void* d_out, int out_size) {
    const float* E = (const float*)d_in[0];
    const void* lab = d_in[1];
    (void)in_sizes; (void)n_in; (void)out_size;
    cudaFuncSetAttribute(kFused, cudaFuncAttributeMaxDynamicSharedMemorySize, DYN_SMEM);
    int sms = 148;
    cudaDeviceGetAttribute(&sms, cudaDevAttrMultiProcessorCount, 0);
    // clamp grid to PROVABLE single-wave residency (spin barrier safety)
    int perSM = 1;
    cudaOccupancyMaxActiveBlocksPerMultiprocessor(&perSM, kFused, BTHR, DYN_SMEM);
    if (perSM < 1) perSM = 1;                  // launch_bounds guarantees >= 1
    long cap = (long)perSM * sms;
    int grid = sms < MAXBLK ? sms : MAXBLK;
    if (grid > cap) grid = (int)cap;
    if (grid < 1) grid = 1;
    kFused<<<grid, BTHR, DYN_SMEM>>>(E, lab, (float*)d_out);
}